// round 16
// baseline (speedup 1.0000x reference)
#include <cuda_runtime.h>
#include <cstdint>

// ---------------------------------------------------------------------------
// QuantumDecoder: z -> tanh(z@W_in) -> 4-qubit circuit Z-expectations ->
//                 relu(@W1) -> sigmoid(@W2)
//
// Post-RY circuit is a fixed 16x16 unitary M:
//   z_q = s0^T Re(M^H Z_q M) s0 = sum_{i<=j} S_q[i,j] s_i s_j.
//
// R16: FULLY FUSED single kernel. 2048 blocks x 256 threads x 32 rows.
//   phase A (front): stage z (coalesced, 1 barrier), per-block sim of the
//     16 basis columns -> S table; threads 0-31 compute one row each
//     (dot -> tanh -> s0 -> quadratic forms -> relu) -> h into smem.
//   phase B (gemm): threads 0-195 own 4 output cols, W2 in 34 regs,
//     h broadcast from smem, per-element exp+rcp sigmoid, __stcs stores.
//   gemm is DRAM-write-bound (~37us floor); front work overlaps it since
//   concurrent blocks sit in different phases. h global round-trip gone.
// ---------------------------------------------------------------------------

// ---- packed f32x2 helpers (Blackwell) -------------------------------------
__device__ __forceinline__ unsigned long long pack2(float x, float y) {
    unsigned long long r;
    asm("mov.b64 %0, {%1, %2};" : "=l"(r) : "f"(x), "f"(y));
    return r;
}
__device__ __forceinline__ void unpack2(unsigned long long v, float& x, float& y) {
    asm("mov.b64 {%0, %1}, %2;" : "=f"(x), "=f"(y) : "l"(v));
}
__device__ __forceinline__ unsigned long long ffma2(unsigned long long a,
                                                    unsigned long long b,
                                                    unsigned long long c) {
    unsigned long long d;
    asm("fma.rn.f32x2 %0, %1, %2, %3;" : "=l"(d) : "l"(a), "l"(b), "l"(c));
    return d;
}
__device__ __forceinline__ float sigmoidf_fast(float x) {
    float e = __expf(-x);                 // MUFU.EX2
    return __fdividef(1.0f, 1.0f + e);    // MUFU.RCP
}
__device__ __forceinline__ float tanhf_fast(float x) {
    x = fminf(fmaxf(x, -15.f), 15.f);     // guard exp overflow
    float e = __expf(-2.f * x);
    return __fdividef(1.f - e, 1.f + e);
}

#define ROWS 32
#define ZS4  33    // float4 stride per row (odd -> conflict-free LDS.128)

__global__ void __launch_bounds__(256, 3) qd_fused_kernel(
    const float* __restrict__ z,   const float* __restrict__ W_in,
    const float* __restrict__ b_in, const float* __restrict__ theta,
    const float* __restrict__ W1,  const float* __restrict__ b1,
    const float* __restrict__ W2,  const float* __restrict__ b2,
    float* __restrict__ out)
{
    __shared__ float4 sZ[ROWS * ZS4];     // staged z rows   (~17 KB)
    __shared__ float4 sWin[128];          // W_in [128][4]
    __shared__ float2 sM[16][16];         // sM[x][j] = <x| fixed-circuit |j>
    __shared__ float4 sS4[136];           // symmetric pair coeffs (4 q's)
    __shared__ float  sW1[32];            // W1 [4][8]
    __shared__ float  sb1[8];
    __shared__ float  sbin[4];
    __shared__ ulonglong2 sH[ROWS * 4];   // h rows, duplicated f32x2

    const int tid = threadIdx.x;
    const int r0  = blockIdx.x * ROWS;
    const float4* zg = (const float4*)z;  // [B][32] float4 view

    // ---- stage z: 32 rows x 32 float4, fully coalesced (1 warp = 1 row) ---
#pragma unroll
    for (int i = 0; i < 4; i++) {
        int idx = i * 256 + tid;          // 0..1023
        int row = idx >> 5, c4 = idx & 31;
        sZ[row * ZS4 + c4] = zg[(size_t)(r0 + row) * 32 + c4];
    }
    if (tid < 128) sWin[tid] = ((const float4*)W_in)[tid];
    if (tid < 32)  sW1[tid] = W1[tid];
    if (tid < 8)   sb1[tid] = b1[tid];
    if (tid < 4)   sbin[tid] = b_in[tid];

    // ---- per-block sim of the fixed circuit on basis state |tid> ----------
    if (tid < 16) {
        float2 st[16];
#pragma unroll
        for (int x = 0; x < 16; x++) st[x] = make_float2(0.f, 0.f);
        st[tid] = make_float2(1.f, 0.f);

#pragma unroll
        for (int layer = 0; layer < 2; layer++) {
#pragma unroll
            for (int q = 0; q < 4; q++) {
                float th = theta[layer * 4 + q];
                float ch, sh;
                __sincosf(0.5f * th, &sh, &ch);
                int bit = 1 << q;
#pragma unroll
                for (int a = 0; a < 8; a++) {
                    int i0 = ((a >> q) << (q + 1)) | (a & (bit - 1));
                    int i1 = i0 | bit;
                    float2 x0 = st[i0], x1 = st[i1];
                    // Rx
                    float2 y0 = make_float2(ch * x0.x + sh * x1.y, ch * x0.y - sh * x1.x);
                    float2 y1 = make_float2(ch * x1.x + sh * x0.y, ch * x1.y - sh * x0.x);
                    // Ry
                    float2 z0 = make_float2(ch * y0.x - sh * y1.x, ch * y0.y - sh * y1.y);
                    float2 z1 = make_float2(sh * y0.x + ch * y1.x, sh * y0.y + ch * y1.y);
                    // Rz
                    st[i0] = make_float2(ch * z0.x + sh * z0.y, ch * z0.y - sh * z0.x);
                    st[i1] = make_float2(ch * z1.x - sh * z1.y, ch * z1.y + sh * z1.x);
                }
            }
            const int cs[4] = {0, 1, 2, 3};
            const int ts[4] = {1, 2, 3, 0};
#pragma unroll
            for (int g = 0; g < 4; g++) {
                float2 tmp[16];
                int c = cs[g], t = ts[g];
#pragma unroll
                for (int m = 0; m < 16; m++) tmp[m] = st[m ^ (((m >> c) & 1) << t)];
#pragma unroll
                for (int m = 0; m < 16; m++) st[m] = tmp[m];
            }
        }
#pragma unroll
        for (int x = 0; x < 16; x++) sM[x][tid] = st[x];
    }
    __syncthreads();                      // sM + sZ + sWin ready

    // ---- S table: 544 entries ---------------------------------------------
    for (int e = tid; e < 544; e += 256) {
        int pair = e >> 2, q = e & 3;
        int i = 0, rem = pair;
        while (rem >= 16 - i) { rem -= 16 - i; i++; }
        int j = i + rem;
        float s = 0.f;
#pragma unroll
        for (int x = 0; x < 16; x++) {
            float2 mi = sM[x][i], mj = sM[x][j];
            float d = mi.x * mj.x + mi.y * mj.y;
            s += ((x >> q) & 1) ? -d : d;
        }
        ((float*)sS4)[pair * 4 + q] = (i == j ? 1.f : 2.f) * s;
    }
    __syncthreads();                      // sS4 ready

    // ---- W2 regs: non-front threads load now (overlaps front compute) -----
    unsigned long long w[8][2];
    unsigned long long bb0 = 0, bb1 = 0;
    const float4* W2v = (const float4*)W2;        // [8][196] float4 view
    if (tid >= 32 && tid < 196) {
#pragma unroll
        for (int k = 0; k < 8; k++) {
            float4 wv = W2v[k * 196 + tid];
            w[k][0] = pack2(wv.x, wv.y);
            w[k][1] = pack2(wv.z, wv.w);
        }
        float4 bv = ((const float4*)b2)[tid];
        bb0 = pack2(bv.x, bv.y);
        bb1 = pack2(bv.z, bv.w);
    }

    // ---- phase A: front compute, threads 0..31, one row each --------------
    if (tid < 32) {
        // 1) lat = tanh(z_row @ W_in + b_in)
        const float4* zr = &sZ[tid * ZS4];
        float ax = sbin[0], ay = sbin[1], az = sbin[2], aw = sbin[3];
#pragma unroll 8
        for (int k = 0; k < 32; k++) {
            float4 zv = zr[k];
            float4 wa = sWin[4 * k + 0], wb = sWin[4 * k + 1];
            float4 wc = sWin[4 * k + 2], wd = sWin[4 * k + 3];
            ax = fmaf(zv.x, wa.x, ax); ay = fmaf(zv.x, wa.y, ay);
            az = fmaf(zv.x, wa.z, az); aw = fmaf(zv.x, wa.w, aw);
            ax = fmaf(zv.y, wb.x, ax); ay = fmaf(zv.y, wb.y, ay);
            az = fmaf(zv.y, wb.z, az); aw = fmaf(zv.y, wb.w, aw);
            ax = fmaf(zv.z, wc.x, ax); ay = fmaf(zv.z, wc.y, ay);
            az = fmaf(zv.z, wc.z, az); aw = fmaf(zv.z, wc.w, aw);
            ax = fmaf(zv.w, wd.x, ax); ay = fmaf(zv.w, wd.y, ay);
            az = fmaf(zv.w, wd.z, az); aw = fmaf(zv.w, wd.w, aw);
        }
        float a0 = tanhf_fast(ax), a1 = tanhf_fast(ay);
        float a2 = tanhf_fast(az), a3 = tanhf_fast(aw);

        // 2) s0: real RY product state
        float c0, s0s, c1, s1s, c2, s2s, c3, s3s;
        __sincosf(0.5f * a0, &s0s, &c0);
        __sincosf(0.5f * a1, &s1s, &c1);
        __sincosf(0.5f * a2, &s2s, &c2);
        __sincosf(0.5f * a3, &s3s, &c3);
        float u0 = c0 * c1, u1 = s0s * c1, u2 = c0 * s1s, u3 = s0s * s1s;
        float v0 = c2 * c3, v1 = s2s * c3, v2 = c2 * s3s, v3 = s2s * s3s;
        float st[16];
        st[0]  = u0 * v0; st[1]  = u1 * v0; st[2]  = u2 * v0; st[3]  = u3 * v0;
        st[4]  = u0 * v1; st[5]  = u1 * v1; st[6]  = u2 * v1; st[7]  = u3 * v1;
        st[8]  = u0 * v2; st[9]  = u1 * v2; st[10] = u2 * v2; st[11] = u3 * v2;
        st[12] = u0 * v3; st[13] = u1 * v3; st[14] = u2 * v3; st[15] = u3 * v3;

        // 3) all 4 quadratic forms via symmetric pair table
        float zq0 = 0.f, zq1 = 0.f, zq2 = 0.f, zq3 = 0.f;
        int pidx = 0;
#pragma unroll
        for (int i = 0; i < 16; i++) {
            float si = st[i];
#pragma unroll
            for (int j = i; j < 16; j++) {
                float p = si * st[j];
                float4 cv = sS4[pidx++];
                zq0 = fmaf(p, cv.x, zq0);
                zq1 = fmaf(p, cv.y, zq1);
                zq2 = fmaf(p, cv.z, zq2);
                zq3 = fmaf(p, cv.w, zq3);
            }
        }

        // 4) h = relu(qexp @ W1 + b1), qexp[k] = zq[3-k]; duplicated f32x2
        unsigned long long hh[8];
#pragma unroll
        for (int m = 0; m < 8; m++) {
            float t = sb1[m];
            t = fmaf(zq3, sW1[0 * 8 + m], t);
            t = fmaf(zq2, sW1[1 * 8 + m], t);
            t = fmaf(zq1, sW1[2 * 8 + m], t);
            t = fmaf(zq0, sW1[3 * 8 + m], t);
            t = fmaxf(t, 0.f);
            hh[m] = pack2(t, t);
        }
        sH[tid * 4 + 0] = make_ulonglong2(hh[0], hh[1]);
        sH[tid * 4 + 1] = make_ulonglong2(hh[2], hh[3]);
        sH[tid * 4 + 2] = make_ulonglong2(hh[4], hh[5]);
        sH[tid * 4 + 3] = make_ulonglong2(hh[6], hh[7]);
    }
    __syncthreads();                      // sH ready

    // ---- front threads fetch their W2 slice now ---------------------------
    if (tid < 32) {
#pragma unroll
        for (int k = 0; k < 8; k++) {
            float4 wv = W2v[k * 196 + tid];
            w[k][0] = pack2(wv.x, wv.y);
            w[k][1] = pack2(wv.z, wv.w);
        }
        float4 bv = ((const float4*)b2)[tid];
        bb0 = pack2(bv.x, bv.y);
        bb1 = pack2(bv.z, bv.w);
    }
    if (tid >= 196) return;

    // ---- phase B: gemm + sigmoid, 4 cols/thread ---------------------------
    float* outp = out + (size_t)r0 * 784 + 4 * tid;

#pragma unroll 4
    for (int rr = 0; rr < ROWS; rr++) {
        ulonglong2 h01 = sH[rr * 4 + 0];
        ulonglong2 h23 = sH[rr * 4 + 1];
        ulonglong2 h45 = sH[rr * 4 + 2];
        ulonglong2 h67 = sH[rr * 4 + 3];

        unsigned long long a0 = bb0, a1 = bb1;
        a0 = ffma2(h01.x, w[0][0], a0);  a1 = ffma2(h01.x, w[0][1], a1);
        a0 = ffma2(h01.y, w[1][0], a0);  a1 = ffma2(h01.y, w[1][1], a1);
        a0 = ffma2(h23.x, w[2][0], a0);  a1 = ffma2(h23.x, w[2][1], a1);
        a0 = ffma2(h23.y, w[3][0], a0);  a1 = ffma2(h23.y, w[3][1], a1);
        a0 = ffma2(h45.x, w[4][0], a0);  a1 = ffma2(h45.x, w[4][1], a1);
        a0 = ffma2(h45.y, w[5][0], a0);  a1 = ffma2(h45.y, w[5][1], a1);
        a0 = ffma2(h67.x, w[6][0], a0);  a1 = ffma2(h67.x, w[6][1], a1);
        a0 = ffma2(h67.y, w[7][0], a0);  a1 = ffma2(h67.y, w[7][1], a1);

        float f0, f1, f2, f3;
        unpack2(a0, f0, f1);
        unpack2(a1, f2, f3);
        __stcs((float4*)(outp + (size_t)rr * 784),
               make_float4(sigmoidf_fast(f0), sigmoidf_fast(f1),
                           sigmoidf_fast(f2), sigmoidf_fast(f3)));
    }
}

// ---------------------------------------------------------------------------
extern "C" void kernel_launch(void* const* d_in, const int* in_sizes, int n_in,
                              void* d_out, int out_size) {
    const float* z     = (const float*)d_in[0];
    const float* W_in  = (const float*)d_in[1];
    const float* b_in  = (const float*)d_in[2];
    const float* theta = (const float*)d_in[3];
    const float* W1    = (const float*)d_in[4];
    const float* b1    = (const float*)d_in[5];
    const float* W2    = (const float*)d_in[6];
    const float* b2    = (const float*)d_in[7];

    int B = in_sizes[0] / 128;          // 65536
    qd_fused_kernel<<<B / ROWS, 256>>>(z, W_in, b_in, theta, W1, b1, W2, b2,
                                       (float*)d_out);
}